// round 1
// baseline (speedup 1.0000x reference)
#include <cuda_runtime.h>

#define H 512
#define W 512
#define NBATCH 32
#define WGROUPS (W / 4)   // 128 groups of 4 pixels per row

__global__ __launch_bounds__(256) void sqdiff_mag_kernel(
    const float* __restrict__ x, float* __restrict__ out)
{
    int idx = blockIdx.x * blockDim.x + threadIdx.x;
    // idx -> (n, h, wg)
    int wg = idx & (WGROUPS - 1);
    int t  = idx >> 7;            // / WGROUPS
    int h  = t & (H - 1);
    int n  = t >> 9;              // / H
    if (n >= NBATCH) return;

    const float* g = x + ((size_t)n * 3 + 1) * (size_t)(H * W);  // channel 1
    int w = wg * 4;

    // Three rows, each covering columns w-1 .. w+4  (6 floats)
    float rm[6], rc[6], rp[6];

    // center row (always in bounds)
    {
        const float* p = g + (size_t)h * W + w;
        float4 v = *reinterpret_cast<const float4*>(p);
        rc[1] = v.x; rc[2] = v.y; rc[3] = v.z; rc[4] = v.w;
        rc[0] = (w > 0)       ? __ldg(p - 1) : 0.0f;
        rc[5] = (w + 4 < W)   ? __ldg(p + 4) : 0.0f;
    }
    // row above
    if (h > 0) {
        const float* p = g + (size_t)(h - 1) * W + w;
        float4 v = *reinterpret_cast<const float4*>(p);
        rm[1] = v.x; rm[2] = v.y; rm[3] = v.z; rm[4] = v.w;
        rm[0] = (w > 0)     ? __ldg(p - 1) : 0.0f;
        rm[5] = (w + 4 < W) ? __ldg(p + 4) : 0.0f;
    } else {
        #pragma unroll
        for (int i = 0; i < 6; i++) rm[i] = 0.0f;
    }
    // row below
    if (h + 1 < H) {
        const float* p = g + (size_t)(h + 1) * W + w;
        float4 v = *reinterpret_cast<const float4*>(p);
        rp[1] = v.x; rp[2] = v.y; rp[3] = v.z; rp[4] = v.w;
        rp[0] = (w > 0)     ? __ldg(p - 1) : 0.0f;
        rp[5] = (w + 4 < W) ? __ldg(p + 4) : 0.0f;
    } else {
        #pragma unroll
        for (int i = 0; i < 6; i++) rp[i] = 0.0f;
    }

    float4 res;
    float* resp = reinterpret_cast<float*>(&res);

    #pragma unroll
    for (int i = 0; i < 4; i++) {
        float c = rc[i + 1];
        // 8 neighbor differences: center minus each neighbor (zero-padded)
        float d0 = c - rc[i + 2];  // right
        float d1 = c - rc[i];      // left
        float d2 = c - rp[i + 1];  // down
        float d3 = c - rm[i + 1];  // up
        float d4 = c - rp[i + 2];  // down-right
        float d5 = c - rp[i];      // down-left
        float d6 = c - rm[i + 2];  // up-right
        float d7 = c - rm[i];      // up-left
        float s = d0 * d0;
        s = fmaf(d1, d1, s);
        s = fmaf(d2, d2, s);
        s = fmaf(d3, d3, s);
        s = fmaf(d4, d4, s);
        s = fmaf(d5, d5, s);
        s = fmaf(d6, d6, s);
        s = fmaf(d7, d7, s);
        resp[i] = sqrtf(s);
    }

    // Write mag to all 3 output channels
    float* ob = out + (size_t)n * 3 * H * W + (size_t)h * W + w;
    *reinterpret_cast<float4*>(ob)                   = res;
    *reinterpret_cast<float4*>(ob + (size_t)H * W)   = res;
    *reinterpret_cast<float4*>(ob + (size_t)2 * H * W) = res;
}

extern "C" void kernel_launch(void* const* d_in, const int* in_sizes, int n_in,
                              void* d_out, int out_size)
{
    const float* x = (const float*)d_in[0];
    float* out = (float*)d_out;
    // s = p = 1 per problem setup (d_in[1], d_in[2] are constant scalars)

    int total_threads = NBATCH * H * WGROUPS;   // 32*512*128 = 2,097,152
    int block = 256;
    int grid = (total_threads + block - 1) / block;
    sqdiff_mag_kernel<<<grid, block>>>(x, out);
}